// round 15
// baseline (speedup 1.0000x reference)
#include <cuda_runtime.h>
#include <math.h>

#define Bc   16
#define Cc   3
#define Rc   512
#define Ac   512
#define Gc   4096
#define Kc   4
#define NS   41     // shifts -20..+20
#define Qc   4      // 3 channels + channel-sum

// Transposed SAT layout: value SAT[r][a] stored at slice[BOFF + a*RPT + r]
#define RPT  544
#define BOFF 31
#define SST  (513 * RPT + 64)

// Static scratch
__device__ float g_y[(size_t)Bc * Qc * Rc * Ac];    // row-cumsum
__device__ float g_satc[(size_t)Bc * Cc * SST];     // transposed per-channel SAT
__device__ float g_sata[(size_t)Bc * SST];          // transposed channel-sum SAT
__device__ float g_w[NS];                           // w[s] = exp(-|s-20|/200)

// ---- one XLA ReduceWindowRewriter(base=16) scan over 512 elems, in-block ---
__device__ __forceinline__ void scan_block(float (&px)[16], float* dst,
                                           int t, int tx, float (*s_tot)[33])
{
    #pragma unroll
    for (int j = 1; j < 16; j++) px[j] = __fadd_rn(px[j-1], px[j]);
    s_tot[t][tx] = px[15];
    __syncthreads();

    if (t == 0) {
        float acc = s_tot[0][tx];                    // incT[0]
        #pragma unroll
        for (int t2 = 1; t2 < 16; t2++) {
            float T = s_tot[t2][tx];
            s_tot[t2][tx] = acc;                     // carry[t2] = incT[t2-1]
            acc = __fadd_rn(acc, T);
        }
        float U0  = acc;                             // fold of T[0..15]
        float T16 = s_tot[16][tx];
        s_tot[16][tx] = acc;                         // carry[16] = incT[15]
        float acch = T16;
        acc = __fadd_rn(U0, acch);                   // incT[16]
        #pragma unroll
        for (int t2 = 17; t2 < 32; t2++) {
            float T = s_tot[t2][tx];
            s_tot[t2][tx] = acc;                     // carry[t2] = incT[t2-1]
            acch = __fadd_rn(acch, T);
            acc = __fadd_rn(U0, acch);
        }
    }
    __syncthreads();

    const float carry = s_tot[t][tx];
    #pragma unroll
    for (int j = 0; j < 16; j++) {
        float o = (t == 0) ? px[j] : __fadd_rn(carry, px[j]);
        dst[(size_t)j * Ac] = o;
    }
    __syncthreads();
}

// ---------------- K1: fused row-axis scans — single pred read ---------------
__global__ void __launch_bounds__(1024) k_rowscan(const float* __restrict__ pred)
{
    if (blockIdx.x == 0 && threadIdx.x < NS) {
        const int sh = (int)threadIdx.x - 20;
        float xw = __fdiv_rn(-(float)(sh < 0 ? -sh : sh), 200.0f);
        g_w[threadIdx.x] = (float)exp((double)xw);
    }

    const int blk  = blockIdx.x;          // 0..255
    const int acol = blk & 15;
    const int b    = blk >> 4;
    const int tx   = threadIdx.x & 31;
    const int t    = threadIdx.x >> 5;    // tile 0..31
    const int a    = acol * 32 + tx;

    __shared__ float s_tot[32][33];

    const float* p  = pred + ((size_t)b * Cc * Rc) * Ac + a;
    float*       yb = g_y  + ((size_t)b * Qc * Rc) * Ac + a;

    float ps[16];   // running channel sum, exact (v0+v1)+v2 order

    #pragma unroll
    for (int c = 0; c < 3; c++) {
        float px[16];
        const float* pc = p + ((size_t)c * Rc + (size_t)t * 16) * Ac;
        #pragma unroll
        for (int j = 0; j < 16; j++) px[j] = __ldg(pc + (size_t)j * Ac);
        #pragma unroll
        for (int j = 0; j < 16; j++)
            ps[j] = (c == 0) ? px[j] : __fadd_rn(ps[j], px[j]);
        scan_block(px, yb + ((size_t)c * Rc + (size_t)t * 16) * Ac, t, tx, s_tot);
    }
    scan_block(ps, yb + ((size_t)3 * Rc + (size_t)t * 16) * Ac, t, tx, s_tot);
}

// ---------------- K2: col-axis scans -> TRANSPOSED SAT (no smem staging) ----
// Thread (ty,t): row r = rblk*16+ty, a-tile t. Direct 4x LDG.128 of the 64
// contiguous bytes g_y[r][16t..16t+15]; same scan DAG; transposed store.
__global__ void __launch_bounds__(512) k_colscan()
{
    const int blk  = blockIdx.x;           // (b,q,rblk): 16*4*32
    const int rblk = blk & 31;
    const int q    = (blk >> 5) & 3;
    const int b    = blk >> 7;
    const int tid  = threadIdx.x;
    const int ty   = tid & 15;              // row in stripe
    const int t    = tid >> 4;              // a-tile 0..31

    __shared__ float s_tot[16][33];

    const int r = rblk * 16 + ty;
    const float4* src = (const float4*)(g_y + (((size_t)b * Qc + q) * Rc + r) * Ac) + t * 4;

    float px[16];
    {
        float4 v0 = __ldg(src + 0);
        float4 v1 = __ldg(src + 1);
        float4 v2 = __ldg(src + 2);
        float4 v3 = __ldg(src + 3);
        px[0]=v0.x;  px[1]=v0.y;  px[2]=v0.z;  px[3]=v0.w;
        px[4]=v1.x;  px[5]=v1.y;  px[6]=v1.z;  px[7]=v1.w;
        px[8]=v2.x;  px[9]=v2.y;  px[10]=v2.z; px[11]=v2.w;
        px[12]=v3.x; px[13]=v3.y; px[14]=v3.z; px[15]=v3.w;
    }
    #pragma unroll
    for (int j = 1; j < 16; j++) px[j] = __fadd_rn(px[j-1], px[j]);
    s_tot[ty][t] = px[15];
    __syncthreads();

    if (t == 0) {   // threads 0..15: fold row ty's 32 totals, exact order
        float acc = s_tot[ty][0];
        #pragma unroll
        for (int t2 = 1; t2 < 16; t2++) {
            float T = s_tot[ty][t2];
            s_tot[ty][t2] = acc;
            acc = __fadd_rn(acc, T);
        }
        float U0  = acc;
        float T16 = s_tot[ty][16];
        s_tot[ty][16] = acc;
        float acch = T16;
        acc = __fadd_rn(U0, acch);
        #pragma unroll
        for (int t2 = 17; t2 < 32; t2++) {
            float T = s_tot[ty][t2];
            s_tot[ty][t2] = acc;
            acch = __fadd_rn(acch, T);
            acc = __fadd_rn(U0, acch);
        }
    }
    __syncthreads();

    const float carry = s_tot[ty][t];
    float* dstb = (q < 3)
        ? g_satc + (size_t)(b * Cc + q) * SST + BOFF
        : g_sata + (size_t)b * SST + BOFF;

    #pragma unroll
    for (int j = 0; j < 16; j++) {
        float o = (t == 0) ? px[j] : __fadd_rn(carry, px[j]);
        int a = t * 16 + j;
        dstb[(size_t)(a + 1) * RPT + (r + 1)] = o;
    }

    if (rblk == 0) {
        for (int i = tid; i < 513; i += 512) {
            dstb[i] = 0.f;                     // r = 0 plane (contiguous in r? no: a plane)
            dstb[(size_t)i * RPT] = 0.f;       // a = 0 plane
        }
    }
}

// ---------------- K3: per-detection vals; warp-0 epilogue -------------------
__global__ void __launch_bounds__(192) k_detect(
    const int* __restrict__ det_b, const int* __restrict__ det_c,
    const int* __restrict__ det_r, const int* __restrict__ det_a,
    const int* __restrict__ radus, const float* __restrict__ pred,
    float* __restrict__ out)
{
    const int g = blockIdx.x;
    const int t = threadIdx.x;

    __shared__ float v3[Kc][NS];

    if (t < Kc * NS) {
        const int k  = t / NS;
        const int s  = t % NS;
        const int sh = s - 20;
        const int gk = g * Kc + k;
        const int dr = det_r[gk], da = det_a[gk], db = det_b[gk];
        const int dc = det_c[gk], rad = radus[gk];

        const int rc = dr + sh;
        const int r1 = min(max(rc - rad, 0), Rc);
        const int r2 = min(max(rc + rad + 1, 0), Rc);
        const int a1 = min(max(da - 2, 0), Ac);
        const int a2 = min(max(da + 3, 0), Ac);

        const float w = g_w[s];

        const float* sc = g_satc + (size_t)(db * Cc + dc) * SST + BOFF;
        const float* sa = g_sata + (size_t)db * SST + BOFF;

        float c22 = __ldg(sc + (size_t)a2 * RPT + r2), c12 = __ldg(sc + (size_t)a2 * RPT + r1);
        float c21 = __ldg(sc + (size_t)a1 * RPT + r2), c11 = __ldg(sc + (size_t)a1 * RPT + r1);
        float rect4 = __fadd_rn(__fsub_rn(__fsub_rn(c22, c12), c21), c11);
        float val1  = __fmul_rn(rect4, w);

        float d22 = __ldg(sa + (size_t)a2 * RPT + r2), d12 = __ldg(sa + (size_t)a2 * RPT + r1);
        float d21 = __ldg(sa + (size_t)a1 * RPT + r2), d11 = __ldg(sa + (size_t)a1 * RPT + r1);
        float rect3 = __fadd_rn(__fsub_rn(__fsub_rn(d22, d12), d21), d11);
        float val2  = __fmul_rn(rect3, w);

        float val3 = __fadd_rn(__fmul_rn(0.5f, val1),
                               __fmul_rn(0.5f, __fsub_rn(val2, val1)));
        v3[k][s] = val3;
    }
    __syncthreads();

    if (t < 32) {   // warp 0 epilogue
        const int s1 = t;
        float bv;
        int   bi = s1;
        float se1 = __fadd_rn(__fadd_rn(__fadd_rn(v3[0][s1], v3[1][s1]), v3[2][s1]), v3[3][s1]);
        out[(size_t)g * NS + s1] = se1;
        bv = se1;
        const int s2 = t + 32;
        if (s2 < NS) {
            float se2 = __fadd_rn(__fadd_rn(__fadd_rn(v3[0][s2], v3[1][s2]), v3[2][s2]), v3[3][s2]);
            out[(size_t)g * NS + s2] = se2;
            if (se2 > bv) { bv = se2; bi = s2; }
        }
        #pragma unroll
        for (int off = 16; off > 0; off >>= 1) {
            float ov = __shfl_xor_sync(0xffffffffu, bv, off);
            int   oi = __shfl_xor_sync(0xffffffffu, bi, off);
            if (ov > bv || (ov == bv && oi < bi)) { bv = ov; bi = oi; }
        }
        const int shift = bi - 20;

        float pmv = 0.3f;
        if (t < 12) {
            const int kk = t / 3, cch = t % 3;
            const int gg = g * Kc + kk;
            const int rr = min(max(det_r[gg] + shift, 0), Rc - 1);
            const int db = det_b[gg], da = det_a[gg];
            pmv = fmaxf(pmv, __ldg(pred + (((size_t)db * Cc + cch) * Rc + rr) * Ac + da));
        }
        #pragma unroll
        for (int off = 16; off > 0; off >>= 1)
            pmv = fmaxf(pmv, __shfl_xor_sync(0xffffffffu, pmv, off));

        if (t == 0) {
            out[(size_t)Gc * NS       + g] = (float)shift;
            out[(size_t)Gc * (NS + 1) + g] = bv;
            out[(size_t)Gc * (NS + 2) + g] = pmv;
        }
    }
}

extern "C" void kernel_launch(void* const* d_in, const int* in_sizes, int n_in,
                              void* d_out, int out_size)
{
    const float* pred  = (const float*)d_in[0];
    const int*   det_b = (const int*)  d_in[1];
    const int*   det_c = (const int*)  d_in[2];
    const int*   det_r = (const int*)  d_in[3];
    const int*   det_a = (const int*)  d_in[4];
    const int*   radus = (const int*)  d_in[5];
    float*       out   = (float*)d_out;

    k_rowscan<<<Bc * (Ac / 32), 1024>>>(pred);   // serial, full grids (R9 structure)
    k_colscan<<<Bc * Qc * 32, 512>>>();
    k_detect<<<Gc, 192>>>(det_b, det_c, det_r, det_a, radus, pred, out);
}

// round 16
// speedup vs baseline: 1.0752x; 1.0752x over previous
#include <cuda_runtime.h>
#include <math.h>

#define Bc   16
#define Cc   3
#define Rc   512
#define Ac   512
#define Gc   4096
#define Kc   4
#define NS   41     // shifts -20..+20
#define Qc   4      // 3 channels + channel-sum

// Transposed SAT layout: value SAT[r][a] stored at slice[BOFF + a*RPT + r]
#define RPT  544
#define BOFF 31
#define SST  (513 * RPT + 64)

// K2 smem staging: row stride 644 (=4 mod 32 -> <=2-way conflicts), tile stride 20
#define SROW 644

// Static scratch
__device__ float g_y[(size_t)Bc * Qc * Rc * Ac];    // row-cumsum
__device__ float g_satc[(size_t)Bc * Cc * SST];     // transposed per-channel SAT
__device__ float g_sata[(size_t)Bc * SST];          // transposed channel-sum SAT
__device__ float g_w[NS];                           // w[s] = exp(-|s-20|/200)

// ---- one XLA ReduceWindowRewriter(base=16) scan over 512 elems, in-block ---
__device__ __forceinline__ void scan_block(float (&px)[16], float* dst,
                                           int t, int tx, float (*s_tot)[33])
{
    #pragma unroll
    for (int j = 1; j < 16; j++) px[j] = __fadd_rn(px[j-1], px[j]);
    s_tot[t][tx] = px[15];
    __syncthreads();

    if (t == 0) {
        float acc = s_tot[0][tx];                    // incT[0]
        #pragma unroll
        for (int t2 = 1; t2 < 16; t2++) {
            float T = s_tot[t2][tx];
            s_tot[t2][tx] = acc;                     // carry[t2] = incT[t2-1]
            acc = __fadd_rn(acc, T);
        }
        float U0  = acc;                             // fold of T[0..15]
        float T16 = s_tot[16][tx];
        s_tot[16][tx] = acc;                         // carry[16] = incT[15]
        float acch = T16;
        acc = __fadd_rn(U0, acch);                   // incT[16]
        #pragma unroll
        for (int t2 = 17; t2 < 32; t2++) {
            float T = s_tot[t2][tx];
            s_tot[t2][tx] = acc;                     // carry[t2] = incT[t2-1]
            acch = __fadd_rn(acch, T);
            acc = __fadd_rn(U0, acch);
        }
    }
    __syncthreads();

    const float carry = s_tot[t][tx];
    #pragma unroll
    for (int j = 0; j < 16; j++) {
        float o = (t == 0) ? px[j] : __fadd_rn(carry, px[j]);
        dst[(size_t)j * Ac] = o;
    }
    __syncthreads();
}

// ---------------- K1: fused row-axis scans — single pred read (R9) ----------
__global__ void __launch_bounds__(1024) k_rowscan(const float* __restrict__ pred)
{
    if (blockIdx.x == 0 && threadIdx.x < NS) {
        const int sh = (int)threadIdx.x - 20;
        float xw = __fdiv_rn(-(float)(sh < 0 ? -sh : sh), 200.0f);
        g_w[threadIdx.x] = (float)exp((double)xw);
    }

    const int blk  = blockIdx.x;          // 0..255
    const int acol = blk & 15;
    const int b    = blk >> 4;
    const int tx   = threadIdx.x & 31;
    const int t    = threadIdx.x >> 5;    // tile 0..31
    const int a    = acol * 32 + tx;

    __shared__ float s_tot[32][33];

    const float* p  = pred + ((size_t)b * Cc * Rc) * Ac + a;
    float*       yb = g_y  + ((size_t)b * Qc * Rc) * Ac + a;

    float ps[16];   // running channel sum, exact (v0+v1)+v2 order

    #pragma unroll
    for (int c = 0; c < 3; c++) {
        float px[16];
        const float* pc = p + ((size_t)c * Rc + (size_t)t * 16) * Ac;
        #pragma unroll
        for (int j = 0; j < 16; j++) px[j] = __ldg(pc + (size_t)j * Ac);
        #pragma unroll
        for (int j = 0; j < 16; j++)
            ps[j] = (c == 0) ? px[j] : __fadd_rn(ps[j], px[j]);
        scan_block(px, yb + ((size_t)c * Rc + (size_t)t * 16) * Ac, t, tx, s_tot);
    }
    scan_block(ps, yb + ((size_t)3 * Rc + (size_t)t * 16) * Ac, t, tx, s_tot);
}

// ---------------- K2: col-axis scans -> TRANSPOSED SAT (float4 staging) -----
__global__ void __launch_bounds__(512) k_colscan()
{
    const int blk  = blockIdx.x;           // (b,q,rblk): 16*4*32
    const int rblk = blk & 31;
    const int q    = (blk >> 5) & 3;
    const int b    = blk >> 7;
    const int tid  = threadIdx.x;
    const int ty   = tid & 15;              // row in stripe
    const int t    = tid >> 4;              // a-tile 0..31

    __shared__ __align__(16) float s_in[16 * SROW];   // tile-padded staging
    __shared__ float s_tot[16][33];

    // phase 1: coalesced float4 stripe load (16 x 512) -> padded smem, STS.128
    const float4* src = (const float4*)(g_y +
        (((size_t)b * Qc + q) * Rc + (size_t)rblk * 16) * Ac);
    #pragma unroll
    for (int i = 0; i < 4; i++) {
        int idx = i * 512 + tid;            // 0..2047 float4s
        int rr  = idx >> 7;                 // row 0..15
        int c4  = idx & 127;                // float4 column
        float4 v = __ldg(src + rr * 128 + c4);
        int cc = c4 * 4;
        *(float4*)&s_in[rr * SROW + (cc >> 4) * 20 + (cc & 15)] = v;
    }
    __syncthreads();

    // phase 2: inner sequential prefix along a (exact acc_inner order)
    float px[16];
    {
        const float* bp = &s_in[ty * SROW + t * 20];
        float4 v0 = *(const float4*)(bp + 0);
        float4 v1 = *(const float4*)(bp + 4);
        float4 v2 = *(const float4*)(bp + 8);
        float4 v3 = *(const float4*)(bp + 12);
        px[0]=v0.x;  px[1]=v0.y;  px[2]=v0.z;  px[3]=v0.w;
        px[4]=v1.x;  px[5]=v1.y;  px[6]=v1.z;  px[7]=v1.w;
        px[8]=v2.x;  px[9]=v2.y;  px[10]=v2.z; px[11]=v2.w;
        px[12]=v3.x; px[13]=v3.y; px[14]=v3.z; px[15]=v3.w;
    }
    #pragma unroll
    for (int j = 1; j < 16; j++) px[j] = __fadd_rn(px[j-1], px[j]);
    s_tot[ty][t] = px[15];
    __syncthreads();

    // phase 3: totals fold per row (exact low/U0/high order)
    if (t == 0) {
        float acc = s_tot[ty][0];
        #pragma unroll
        for (int t2 = 1; t2 < 16; t2++) {
            float T = s_tot[ty][t2];
            s_tot[ty][t2] = acc;
            acc = __fadd_rn(acc, T);
        }
        float U0  = acc;
        float T16 = s_tot[ty][16];
        s_tot[ty][16] = acc;
        float acch = T16;
        acc = __fadd_rn(U0, acch);
        #pragma unroll
        for (int t2 = 17; t2 < 32; t2++) {
            float T = s_tot[ty][t2];
            s_tot[ty][t2] = acc;
            acch = __fadd_rn(acch, T);
            acc = __fadd_rn(U0, acch);
        }
    }
    __syncthreads();

    const float carry = s_tot[ty][t];
    float* dstb = (q < 3)
        ? g_satc + (size_t)(b * Cc + q) * SST + BOFF
        : g_sata + (size_t)b * SST + BOFF;
    const int r = rblk * 16 + ty;

    #pragma unroll
    for (int j = 0; j < 16; j++) {
        float o = (t == 0) ? px[j] : __fadd_rn(carry, px[j]);
        int a = t * 16 + j;
        dstb[(size_t)(a + 1) * RPT + (r + 1)] = o;   // sat_T[a+1][r+1]
    }

    if (rblk == 0) {   // fused borders: sat_T[0][*] and sat_T[*][0]
        for (int i = tid; i < 513; i += 512) {
            dstb[i] = 0.f;
            dstb[(size_t)i * RPT] = 0.f;
        }
    }
}

// ---------------- K3: per-detection vals; warp-0 epilogue (R9) --------------
__global__ void __launch_bounds__(192) k_detect(
    const int* __restrict__ det_b, const int* __restrict__ det_c,
    const int* __restrict__ det_r, const int* __restrict__ det_a,
    const int* __restrict__ radus, const float* __restrict__ pred,
    float* __restrict__ out)
{
    const int g = blockIdx.x;
    const int t = threadIdx.x;

    __shared__ float v3[Kc][NS];

    if (t < Kc * NS) {
        const int k  = t / NS;
        const int s  = t % NS;
        const int sh = s - 20;
        const int gk = g * Kc + k;
        const int dr = det_r[gk], da = det_a[gk], db = det_b[gk];
        const int dc = det_c[gk], rad = radus[gk];

        const int rc = dr + sh;
        const int r1 = min(max(rc - rad, 0), Rc);
        const int r2 = min(max(rc + rad + 1, 0), Rc);
        const int a1 = min(max(da - 2, 0), Ac);
        const int a2 = min(max(da + 3, 0), Ac);

        const float w = g_w[s];

        const float* sc = g_satc + (size_t)(db * Cc + dc) * SST + BOFF;
        const float* sa = g_sata + (size_t)db * SST + BOFF;

        float c22 = __ldg(sc + (size_t)a2 * RPT + r2), c12 = __ldg(sc + (size_t)a2 * RPT + r1);
        float c21 = __ldg(sc + (size_t)a1 * RPT + r2), c11 = __ldg(sc + (size_t)a1 * RPT + r1);
        float rect4 = __fadd_rn(__fsub_rn(__fsub_rn(c22, c12), c21), c11);
        float val1  = __fmul_rn(rect4, w);

        float d22 = __ldg(sa + (size_t)a2 * RPT + r2), d12 = __ldg(sa + (size_t)a2 * RPT + r1);
        float d21 = __ldg(sa + (size_t)a1 * RPT + r2), d11 = __ldg(sa + (size_t)a1 * RPT + r1);
        float rect3 = __fadd_rn(__fsub_rn(__fsub_rn(d22, d12), d21), d11);
        float val2  = __fmul_rn(rect3, w);

        float val3 = __fadd_rn(__fmul_rn(0.5f, val1),
                               __fmul_rn(0.5f, __fsub_rn(val2, val1)));
        v3[k][s] = val3;
    }
    __syncthreads();

    if (t < 32) {   // warp 0 epilogue
        const int s1 = t;
        float bv;
        int   bi = s1;
        float se1 = __fadd_rn(__fadd_rn(__fadd_rn(v3[0][s1], v3[1][s1]), v3[2][s1]), v3[3][s1]);
        out[(size_t)g * NS + s1] = se1;
        bv = se1;
        const int s2 = t + 32;
        if (s2 < NS) {
            float se2 = __fadd_rn(__fadd_rn(__fadd_rn(v3[0][s2], v3[1][s2]), v3[2][s2]), v3[3][s2]);
            out[(size_t)g * NS + s2] = se2;
            if (se2 > bv) { bv = se2; bi = s2; }
        }
        #pragma unroll
        for (int off = 16; off > 0; off >>= 1) {
            float ov = __shfl_xor_sync(0xffffffffu, bv, off);
            int   oi = __shfl_xor_sync(0xffffffffu, bi, off);
            if (ov > bv || (ov == bv && oi < bi)) { bv = ov; bi = oi; }
        }
        const int shift = bi - 20;

        float pmv = 0.3f;
        if (t < 12) {
            const int kk = t / 3, cch = t % 3;
            const int gg = g * Kc + kk;
            const int rr = min(max(det_r[gg] + shift, 0), Rc - 1);
            const int db = det_b[gg], da = det_a[gg];
            pmv = fmaxf(pmv, __ldg(pred + (((size_t)db * Cc + cch) * Rc + rr) * Ac + da));
        }
        #pragma unroll
        for (int off = 16; off > 0; off >>= 1)
            pmv = fmaxf(pmv, __shfl_xor_sync(0xffffffffu, pmv, off));

        if (t == 0) {
            out[(size_t)Gc * NS       + g] = (float)shift;
            out[(size_t)Gc * (NS + 1) + g] = bv;
            out[(size_t)Gc * (NS + 2) + g] = pmv;
        }
    }
}

extern "C" void kernel_launch(void* const* d_in, const int* in_sizes, int n_in,
                              void* d_out, int out_size)
{
    const float* pred  = (const float*)d_in[0];
    const int*   det_b = (const int*)  d_in[1];
    const int*   det_c = (const int*)  d_in[2];
    const int*   det_r = (const int*)  d_in[3];
    const int*   det_a = (const int*)  d_in[4];
    const int*   radus = (const int*)  d_in[5];
    float*       out   = (float*)d_out;

    k_rowscan<<<Bc * (Ac / 32), 1024>>>(pred);
    k_colscan<<<Bc * Qc * 32, 512>>>();
    k_detect<<<Gc, 192>>>(det_b, det_c, det_r, det_a, radus, pred, out);
}